// round 14
// baseline (speedup 1.0000x reference)
#include <cuda_runtime.h>
#include <cuda.h>
#include <cuda_fp16.h>
#include <math.h>

#define FULLMASK 0xFFFFFFFFu
#define BT    64
#define PDIM  1024
#define CDIM  1024
#define TT    8
#define RANK  32
#define DST   16
#define MROWS (BT * PDIM)
#define KPAD  1088
#define SCALING 4.0f
#define NRP   96

#if defined(__CUDA_ARCH_FEAT_SM103_ALL) || defined(__CUDA_ARCH_FEAT_SM100_ALL) || defined(__CUDA_ARCH_FEAT_SM101_ALL)
#define HAS_TC 1
#endif

__device__ __align__(128) __half g_xh[(size_t)MROWS * KPAD];
__device__ __align__(128) __half g_wh[(size_t)CDIM * KPAD];
__device__ __align__(128) __half g_wch[(size_t)NRP * CDIM];
__device__ float g_rp[(size_t)MROWS * NRP];
__device__ float g_bbe[CDIM];

// ---------------- PTX helpers ----------------
__device__ __forceinline__ uint32_t smem_u32(const void* p) {
    uint32_t a;
    asm("{ .reg .u64 t; cvta.to.shared.u64 t, %1; cvt.u32.u64 %0, t; }" : "=r"(a) : "l"(p));
    return a;
}
#define MBAR_INIT(a, c) asm volatile("mbarrier.init.shared.b64 [%0], %1;" :: "r"(a), "r"(c) : "memory")
#define MBAR_ARRIVE(a)  asm volatile("mbarrier.arrive.shared.b64 _, [%0];" :: "r"(a) : "memory")
#define MBAR_EXPECT_TX(a, b) asm volatile("mbarrier.arrive.expect_tx.shared.b64 _, [%0], %1;" :: "r"(a), "r"(b) : "memory")
#define MBAR_WAIT(a, p) do { \
    asm volatile("{\n\t.reg .pred P1;\n\tWL_%=:\n\t" \
        "mbarrier.try_wait.parity.acquire.cta.shared::cta.b64 P1, [%0], %1, 0x989680;\n\t" \
        "@P1 bra.uni WD_%=;\n\tbra.uni WL_%=;\n\tWD_%=:\n\t}" :: "r"(a), "r"(p) : "memory"); \
} while (0)
#define TMA_LOAD_2D(dst, tm, cx, cy, mb) \
    asm volatile("cp.async.bulk.tensor.2d.shared::cta.global.tile.mbarrier::complete_tx::bytes " \
        "[%0], [%1, {%2, %3}], [%4];" :: "r"(dst), "l"(tm), "r"(cx), "r"(cy), "r"(mb) : "memory")

#ifdef HAS_TC
#define TC_ALLOC(s, n) asm volatile("tcgen05.alloc.cta_group::1.sync.aligned.shared::cta.b32 [%0], %1;" :: "r"(s), "r"(n) : "memory")
#define TC_RELINQ()    asm volatile("tcgen05.relinquish_alloc_permit.cta_group::1.sync.aligned;")
#define TC_DEALLOC(t, n) asm volatile("tcgen05.dealloc.cta_group::1.sync.aligned.b32 %0, %1;" :: "r"(t), "r"(n))
#define TC_COMMIT(mb)  asm volatile("tcgen05.commit.cta_group::1.mbarrier::arrive::one.shared::cluster.b64 [%0];" :: "r"(mb) : "memory")
#define TC_FENCE_AFTER() asm volatile("tcgen05.fence::after_thread_sync;" ::: "memory")
#define TC_WAIT_LD()   asm volatile("tcgen05.wait::ld.sync.aligned;" ::: "memory")

__device__ __forceinline__ void mma_f16_ss(uint32_t d, uint64_t ad, uint64_t bd,
                                           uint32_t idesc, uint32_t accf) {
    asm volatile("{\n\t.reg .pred p;\n\tsetp.ne.u32 p, %4, 0;\n\t"
        "tcgen05.mma.cta_group::1.kind::f16 [%0], %1, %2, %3, {%5,%5,%5,%5}, p;\n\t}"
        :: "r"(d), "l"(ad), "l"(bd), "r"(idesc), "r"(accf), "r"(0u) : "memory");
}
#define TC_LD_X32(r, t) \
    asm volatile("tcgen05.ld.sync.aligned.32x32b.x32.b32 " \
        "{%0,%1,%2,%3,%4,%5,%6,%7,%8,%9,%10,%11,%12,%13,%14,%15," \
        "%16,%17,%18,%19,%20,%21,%22,%23,%24,%25,%26,%27,%28,%29,%30,%31}, [%32];" \
        : "=r"((r)[0]),"=r"((r)[1]),"=r"((r)[2]),"=r"((r)[3]),"=r"((r)[4]),"=r"((r)[5]),"=r"((r)[6]),"=r"((r)[7]), \
          "=r"((r)[8]),"=r"((r)[9]),"=r"((r)[10]),"=r"((r)[11]),"=r"((r)[12]),"=r"((r)[13]),"=r"((r)[14]),"=r"((r)[15]), \
          "=r"((r)[16]),"=r"((r)[17]),"=r"((r)[18]),"=r"((r)[19]),"=r"((r)[20]),"=r"((r)[21]),"=r"((r)[22]),"=r"((r)[23]), \
          "=r"((r)[24]),"=r"((r)[25]),"=r"((r)[26]),"=r"((r)[27]),"=r"((r)[28]),"=r"((r)[29]),"=r"((r)[30]),"=r"((r)[31]) \
        : "r"(t))
#endif

#define DESC_BASE ((2ull << 61) | (1ull << 46) | (64ull << 32) | (1ull << 16))
#define MAKE_DESC(a) (DESC_BASE | ((uint64_t)((a) >> 4) & 0x3FFF))
#define IDESC_BIG 0x8400010u    /* cg1: F32 acc, f16, M=128, N=256 */
#define IDESC_RP  0x8180010u    /* cg1: F32 acc, f16, M=128, N=96  */

// ---------------- k_prep: fused conv + weight builds ----------------
#define CONV_BLKS 32768
#define WB_BLKS   (CDIM * KPAD / 256)
#define WC_BLKS   (NRP * CDIM / 256)
#define BBE_BLKS  4
#define PREP_BLKS (CONV_BLKS + WB_BLKS + WC_BLKS + BBE_BLKS)

__global__ __launch_bounds__(256) void k_prep(const float* __restrict__ x,
                                              const float* __restrict__ Wb,
                                              const float* __restrict__ Wup,
                                              const float* __restrict__ Wout,
                                              const float* __restrict__ Wdown,
                                              const float* __restrict__ Wxp,
                                              const float* __restrict__ bb,
                                              const float* __restrict__ bout) {
    const int bid = blockIdx.x, tid = threadIdx.x;
    if (bid < CONV_BLKS) {
        size_t base = ((size_t)bid * 256 + tid) * 8;
        size_t row = base >> 10, col = base & 1023;
        float4 v0 = *(const float4*)(x + base);
        float4 v1 = *(const float4*)(x + base + 4);
        __half2 h0 = __floats2half2_rn(v0.x, v0.y);
        __half2 h1 = __floats2half2_rn(v0.z, v0.w);
        __half2 h2 = __floats2half2_rn(v1.x, v1.y);
        __half2 h3 = __floats2half2_rn(v1.z, v1.w);
        uint4 u;
        u.x = *(uint32_t*)&h0; u.y = *(uint32_t*)&h1;
        u.z = *(uint32_t*)&h2; u.w = *(uint32_t*)&h3;
        *(uint4*)(g_xh + row * KPAD + col) = u;
    } else if (bid < CONV_BLKS + WB_BLKS) {
        int idx = (bid - CONV_BLKS) * 256 + tid;
        int n = idx / KPAD, c = idx % KPAD;
        float v;
        if (c < 1024) {
            v = Wb[(size_t)n * 1024 + c];
        } else if (c < 1056) {
            int q = c - 1024;
            float s = 0.f;
#pragma unroll
            for (int r = 0; r < RANK; r++)
                s = fmaf(Wup[(size_t)n * RANK + r], Wout[r * RANK + q], s);
            v = SCALING * s;
        } else v = 0.f;
        g_wh[idx] = __float2half_rn(v);
    } else if (bid < CONV_BLKS + WB_BLKS + WC_BLKS) {
        int idx = (bid - CONV_BLKS - WB_BLKS) * 256 + tid;
        int row = idx >> 10, c = idx & 1023;
        float v;
        if (row < RANK) {
            v = Wdown[(size_t)row * CDIM + c];
        } else {
            int i = row - RANK;
            float s = 0.f;
#pragma unroll
            for (int r = 0; r < RANK; r++)
                s = fmaf(Wxp[i * RANK + r], Wdown[(size_t)r * CDIM + c], s);
            v = s;
        }
        g_wch[idx] = __float2half_rn(v);
    } else {
        int n = (bid - CONV_BLKS - WB_BLKS - WC_BLKS) * 256 + tid;
        if (n < CDIM) {
            float s = 0.f;
#pragma unroll
            for (int r = 0; r < RANK; r++)
                s = fmaf(Wup[(size_t)n * RANK + r], bout[r], s);
            g_bbe[n] = bb[n] + SCALING * s;
        }
    }
}

// ---------------- k_red: rp = xh @ Wcomb.T  (M=65536, N=96, K=1024) ----------------
#define R_KCH    64
#define R_NCH    16
#define R_ABYTES (128 * 128)
#define R_BBYTES (NRP * 128)
#define R_STG    (R_ABYTES + R_BBYTES)
#define R_SMEM   (1024 + 3 * R_STG)

__global__ __launch_bounds__(128) void k_red(const __grid_constant__ CUtensorMap tmA,
                                             const __grid_constant__ CUtensorMap tmWc) {
#ifdef HAS_TC
    extern __shared__ __align__(1024) char smem[];
    const uint32_t sbase = smem_u32(smem);
    const uint32_t tslot = sbase;
    const uint32_t fullb = sbase + 16;
    const uint32_t emptb = sbase + 48;
    const uint32_t doneb = sbase + 80;
    const int tid = threadIdx.x, wid = tid >> 5, lane = tid & 31;
    const int m0 = blockIdx.x * 128;

    if (tid == 0) {
        MBAR_INIT(fullb, 1); MBAR_INIT(fullb + 8, 1); MBAR_INIT(fullb + 16, 1);
        MBAR_INIT(emptb, 1); MBAR_INIT(emptb + 8, 1); MBAR_INIT(emptb + 16, 1);
        MBAR_INIT(doneb, 1);
    }
    if (wid == 0) { TC_ALLOC(tslot, 128); TC_RELINQ(); }
    __syncthreads();
    uint32_t tmem;
    asm volatile("ld.shared.b32 %0, [%1];" : "=r"(tmem) : "r"(tslot));

    if (tid == 0) {
        int eph[3] = {1, 1, 1};
        for (int c = 0; c < R_NCH; c++) {
            int s = c % 3;
            MBAR_WAIT(emptb + s * 8, eph[s]); eph[s] ^= 1;
            uint32_t aA = sbase + 1024 + s * R_STG;
            MBAR_EXPECT_TX(fullb + s * 8, R_STG);
            TMA_LOAD_2D(aA, &tmA, c * R_KCH, m0, fullb + s * 8);
            TMA_LOAD_2D(aA + R_ABYTES, &tmWc, c * R_KCH, 0, fullb + s * 8);
        }
    } else if (tid == 33) {
        int fph[3] = {0, 0, 0};
        for (int c = 0; c < R_NCH; c++) {
            int s = c % 3;
            MBAR_WAIT(fullb + s * 8, fph[s]); fph[s] ^= 1;
            uint32_t aA = sbase + 1024 + s * R_STG;
            uint64_t ad = MAKE_DESC(aA), bd = MAKE_DESC(aA + R_ABYTES);
#pragma unroll
            for (int k = 0; k < 4; k++)
                mma_f16_ss(tmem, ad + 2 * k, bd + 2 * k, IDESC_RP, (c | k) != 0);
            TC_COMMIT(emptb + s * 8);
        }
        TC_COMMIT(doneb);
    }

    MBAR_WAIT(doneb, 0);
    TC_FENCE_AFTER();

    float* gr = g_rp + (size_t)(m0 + wid * 32 + lane) * NRP;
#pragma unroll
    for (int cb = 0; cb < 3; cb++) {
        uint32_t r[32];
        TC_LD_X32(r, tmem + cb * 32);
        TC_WAIT_LD();
#pragma unroll
        for (int j = 0; j < 32; j += 4) {
            float4 v;
            v.x = __uint_as_float(r[j]);     v.y = __uint_as_float(r[j + 1]);
            v.z = __uint_as_float(r[j + 2]); v.w = __uint_as_float(r[j + 3]);
            *(float4*)(gr + cb * 32 + j) = v;
        }
    }
    __syncthreads();
    if (wid == 0) TC_DEALLOC(tmem, 128);
#else
    const int tid = threadIdx.x;
    const int m0 = blockIdx.x * 128;
    for (int e = tid; e < 128 * NRP; e += 128) {
        int r = e / NRP, n = e % NRP;
        float acc = 0.f;
        for (int k = 0; k < CDIM; k++)
            acc = fmaf(__half2float(g_xh[(size_t)(m0 + r) * KPAD + k]),
                       __half2float(g_wch[(size_t)n * CDIM + k]), acc);
        g_rp[(size_t)(m0 + r) * NRP + n] = acc;
    }
#endif
}

// ---------------- k_ssm: pure recurrence ----------------
__device__ __forceinline__ float softplusf(float v) {
    return (v > 15.0f) ? v : log1pf(__expf(v));
}

__global__ __launch_bounds__(256) void k_ssm(const float* __restrict__ A_log,
                                             const float* __restrict__ Dp,
                                             const float* __restrict__ bxp) {
    const int tid  = threadIdx.x;
    const int lane = tid & 31;
    const int seq  = (blockIdx.x * blockDim.x + tid) >> 5;
    const int b = seq >> 10, p = seq & 1023;

    float An[DST];
#pragma unroll
    for (int s = 0; s < DST; s++) An[s] = -__expf(__ldg(A_log + lane * 16 + s));
    const float Dpr  = __ldg(Dp + lane);
    const float bx0  = __ldg(bxp + lane);
    const float bx1  = __ldg(bxp + 32 + lane);
    float h[DST];
#pragma unroll
    for (int s = 0; s < DST; s++) h[s] = 0.f;

    for (int t = 0; t < TT; t++) {
        size_t m = (size_t)(b * TT + t) * PDIM + p;
        const float* rp = g_rp + m * NRP;
        float xv = rp[lane];
        float p0 = rp[32 + lane] + bx0;
        float p1 = rp[64 + lane] + bx1;
        float dlt = softplusf(p0);
        float y = Dpr * xv;
#pragma unroll
        for (int s = 0; s < DST; s++) {
            float Bs_ = __shfl_sync(FULLMASK, p1, s);
            float Cs_ = __shfl_sync(FULLMASK, p1, 16 + s);
            float Ab  = __expf(dlt * An[s]);
            h[s] = fmaf(Ab, h[s], dlt * Bs_ * xv);
            y    = fmaf(h[s], Cs_, y);
        }
        g_xh[m * KPAD + 1024 + lane] = __float2half_rn(y);
        g_xh[m * KPAD + 1056 + lane] = __float2half_rn(0.f);
    }
}

// ---------------- k_big: PERSISTENT cg1 GEMM, double-buffered TMEM accumulators ----------
// 296 CTAs, 384 threads: w0-7 epilogue, w8 lane0 = TMA producer, w9 lane0 = MMA issuer.
// Each CTA loops over tiles (m-major); acc ping-pong (TMEM cols 0 / 256) lets the
// epilogue of tile t overlap the mainloop of tile t+1.
#define KCH       64
#define NCHUNK    17
#define A_BYTES   (128 * 128)
#define B_BYTES   (256 * 128)
#define STG_BYTES (A_BYTES + B_BYTES)      // 49152
#define SMEM_DYN  (1024 + 2 * STG_BYTES)   // 99328
#define NTILES    2048                     // 512 M-tiles x 4 N-tiles
#define PCTAS     296

__global__ __launch_bounds__(384, 2) void k_big(const __grid_constant__ CUtensorMap tmA,
                                                const __grid_constant__ CUtensorMap tmB,
                                                float* __restrict__ out) {
#ifdef HAS_TC
    extern __shared__ __align__(1024) char smem[];
    const uint32_t sbase = smem_u32(smem);
    const uint32_t tslot = sbase;
    const uint32_t fullb = sbase + 16;    // 2 x 8B
    const uint32_t emptb = sbase + 32;    // 2 x 8B
    const uint32_t doneb = sbase + 48;    // accdone[2]
    const uint32_t freeb = sbase + 64;    // accfree[2]

    const int tid = threadIdx.x;
    const int wid = tid >> 5, lane = tid & 31;
    const int bid = blockIdx.x;

    if (tid == 0) {
        MBAR_INIT(fullb, 1); MBAR_INIT(fullb + 8, 1);
        MBAR_INIT(emptb, 1); MBAR_INIT(emptb + 8, 1);
        MBAR_INIT(doneb, 1); MBAR_INIT(doneb + 8, 1);
        MBAR_INIT(freeb, 1); MBAR_INIT(freeb + 8, 1);
    }
    if (wid == 0) { TC_ALLOC(tslot, 512); TC_RELINQ(); }
    __syncthreads();
    uint32_t tmem;
    asm volatile("ld.shared.b32 %0, [%1];" : "=r"(tmem) : "r"(tslot));

    if (tid == 256) {               // ---- producer (w8 lane 0) ----
        int eph[2] = {1, 1};
        int s = 0;
        for (int t = bid; t < NTILES; t += PCTAS) {
            const int m0 = (t & 511) * 128;
            const int n0 = (t >> 9) * 256;
            for (int c = 0; c < NCHUNK; c++) {
                MBAR_WAIT(emptb + s * 8, eph[s]); eph[s] ^= 1;
                uint32_t aA = sbase + 1024 + s * STG_BYTES;
                MBAR_EXPECT_TX(fullb + s * 8, STG_BYTES);
                TMA_LOAD_2D(aA, &tmA, c * KCH, m0, fullb + s * 8);
                TMA_LOAD_2D(aA + A_BYTES, &tmB, c * KCH, n0, fullb + s * 8);
                s ^= 1;
            }
        }
    } else if (tid == 288) {        // ---- MMA issuer (w9 lane 0) ----
        int fph[2] = {0, 0};
        int aph[2] = {1, 1};
        int s = 0, tt = 0;
        for (int t = bid; t < NTILES; t += PCTAS, tt++) {
            const int p = tt & 1;
            MBAR_WAIT(freeb + p * 8, aph[p]); aph[p] ^= 1;   // acc p free?
            const uint32_t dacc = tmem + p * 256;
            for (int c = 0; c < NCHUNK; c++) {
                MBAR_WAIT(fullb + s * 8, fph[s]); fph[s] ^= 1;
                uint32_t aA = sbase + 1024 + s * STG_BYTES;
                uint64_t ad = MAKE_DESC(aA), bd = MAKE_DESC(aA + A_BYTES);
#pragma unroll
                for (int k = 0; k < 4; k++)
                    mma_f16_ss(dacc, ad + 2 * k, bd + 2 * k, IDESC_BIG, (c | k) != 0);
                TC_COMMIT(emptb + s * 8);
                s ^= 1;
            }
            TC_COMMIT(doneb + p * 8);
        }
    } else if (tid < 256) {         // ---- epilogue (w0-7) ----
        int dph[2] = {0, 0};
        int tt = 0;
        const int rbase = (wid & 3) * 32 + lane;
        const int cb0   = (wid >> 2) * 128;
        for (int t = bid; t < NTILES; t += PCTAS, tt++) {
            const int p = tt & 1;
            MBAR_WAIT(doneb + p * 8, dph[p]); dph[p] ^= 1;
            TC_FENCE_AFTER();
            const uint32_t sacc = tmem + p * 256;
            const int row = (t & 511) * 128 + rbase;
            const int n0  = (t >> 9) * 256;
#pragma unroll
            for (int cb = 0; cb < 4; cb++) {
                uint32_t r[32];
                TC_LD_X32(r, sacc + cb0 + cb * 32);
                TC_WAIT_LD();
                const int col = n0 + cb0 + cb * 32;
                float* orow = out + (size_t)row * CDIM + col;
#pragma unroll
                for (int j = 0; j < 32; j += 4) {
                    float4 v;
                    v.x = __uint_as_float(r[j])     + g_bbe[col + j];
                    v.y = __uint_as_float(r[j + 1]) + g_bbe[col + j + 1];
                    v.z = __uint_as_float(r[j + 2]) + g_bbe[col + j + 2];
                    v.w = __uint_as_float(r[j + 3]) + g_bbe[col + j + 3];
                    *(float4*)(orow + j) = v;
                }
            }
            asm volatile("bar.sync 1, 256;" ::: "memory");   // all 8 epi warps done reading
            if (tid == 0) MBAR_ARRIVE(freeb + p * 8);
        }
    }

    __syncthreads();
    if (wid == 0) TC_DEALLOC(tmem, 512);
#else
    // fallback (compile-only for non-'a' pass)
    const int tid = threadIdx.x;
    for (int t = blockIdx.x; t < NTILES; t += PCTAS) {
        const int m0 = (t & 511) * 128;
        const int n0 = (t >> 9) * 256;
        for (int e = tid; e < 128 * 256; e += 384) {
            int r = e >> 8, c = e & 255;
            const __half2* a = (const __half2*)(g_xh + (size_t)(m0 + r) * KPAD);
            const __half2* w = (const __half2*)(g_wh + (size_t)(n0 + c) * KPAD);
            float acc = 0.f;
            for (int k = 0; k < KPAD / 2; k++) {
                float2 av = __half22float2(a[k]);
                float2 wv = __half22float2(w[k]);
                acc = fmaf(av.x, wv.x, acc);
                acc = fmaf(av.y, wv.y, acc);
            }
            out[(size_t)(m0 + r) * CDIM + n0 + c] = acc + g_bbe[n0 + c];
        }
    }
#endif
}

// ---------------- Host ----------------
typedef CUresult (*EncodeFn)(CUtensorMap*, CUtensorMapDataType, cuuint32_t, void*,
                             const cuuint64_t*, const cuuint64_t*, const cuuint32_t*,
                             const cuuint32_t*, CUtensorMapInterleave, CUtensorMapSwizzle,
                             CUtensorMapL2promotion, CUtensorMapFloatOOBfill);

static void make_map(EncodeFn enc, CUtensorMap* tm, void* ptr, uint64_t d0, uint64_t d1,
                     uint32_t b0, uint32_t b1) {
    cuuint64_t dims[2]    = {d0, d1};
    cuuint64_t strides[1] = {d0 * 2};
    cuuint32_t box[2]     = {b0, b1};
    cuuint32_t es[2]      = {1, 1};
    enc(tm, CU_TENSOR_MAP_DATA_TYPE_FLOAT16, 2, ptr, dims, strides, box, es,
        CU_TENSOR_MAP_INTERLEAVE_NONE, CU_TENSOR_MAP_SWIZZLE_128B,
        CU_TENSOR_MAP_L2_PROMOTION_L2_128B, CU_TENSOR_MAP_FLOAT_OOB_FILL_NONE);
}

extern "C" void kernel_launch(void* const* d_in, const int* in_sizes, int n_in,
                              void* d_out, int out_size) {
    const float* x     = (const float*)d_in[0];
    const float* Wb    = (const float*)d_in[1];
    const float* bb    = (const float*)d_in[2];
    const float* Wdown = (const float*)d_in[3];
    const float* Wup   = (const float*)d_in[4];
    const float* A_log = (const float*)d_in[5];
    const float* Dp    = (const float*)d_in[6];
    const float* Wxp   = (const float*)d_in[7];
    const float* bxp   = (const float*)d_in[8];
    const float* Wout  = (const float*)d_in[9];
    const float* bout  = (const float*)d_in[10];
    float* out = (float*)d_out;

    void* fn = nullptr;
    cudaDriverEntryPointQueryResult qr;
    cudaGetDriverEntryPointByVersion("cuTensorMapEncodeTiled", &fn, CUDART_VERSION,
                                     cudaEnableDefault, &qr);
    EncodeFn enc = (EncodeFn)fn;

    void *xh_ptr, *wh_ptr, *wch_ptr;
    cudaGetSymbolAddress(&xh_ptr,  g_xh);
    cudaGetSymbolAddress(&wh_ptr,  g_wh);
    cudaGetSymbolAddress(&wch_ptr, g_wch);

    CUtensorMap tmA, tmB, tmWc;
    make_map(enc, &tmA,  xh_ptr,  KPAD, MROWS, KCH,   128);
    make_map(enc, &tmB,  wh_ptr,  KPAD, CDIM,  KCH,   256);
    make_map(enc, &tmWc, wch_ptr, CDIM, NRP,   R_KCH, NRP);

    cudaFuncSetAttribute(k_big, cudaFuncAttributeMaxDynamicSharedMemorySize, SMEM_DYN);
    cudaFuncSetAttribute(k_red, cudaFuncAttributeMaxDynamicSharedMemorySize, R_SMEM);

    k_prep<<<PREP_BLKS, 256>>>(x, Wb, Wup, Wout, Wdown, Wxp, bb, bout);
    k_red<<<MROWS / 128, 128, R_SMEM>>>(tmA, tmWc);
    k_ssm<<<(MROWS / TT) * 32 / 256, 256>>>(A_log, Dp, bxp);

    k_big<<<PCTAS, 384, SMEM_DYN>>>(tmA, tmB, out);
}

// round 17
// speedup vs baseline: 1.1528x; 1.1528x over previous
#include <cuda_runtime.h>
#include <cuda.h>
#include <cuda_fp16.h>
#include <math.h>

#define FULLMASK 0xFFFFFFFFu
#define BT    64
#define PDIM  1024
#define CDIM  1024
#define TT    8
#define RANK  32
#define DST   16
#define MROWS (BT * PDIM)
#define KPAD  1088
#define SCALING 4.0f
#define NRP   96

#if defined(__CUDA_ARCH_FEAT_SM103_ALL) || defined(__CUDA_ARCH_FEAT_SM100_ALL) || defined(__CUDA_ARCH_FEAT_SM101_ALL)
#define HAS_TC 1
#endif

__device__ __align__(128) __half g_xh[(size_t)MROWS * KPAD];
__device__ __align__(128) __half g_wh[(size_t)CDIM * KPAD];
__device__ __align__(128) __half g_wch[(size_t)NRP * CDIM];
__device__ float g_rp[(size_t)MROWS * NRP];
__device__ float g_bbe[CDIM];

// ---------------- PTX helpers ----------------
__device__ __forceinline__ uint32_t smem_u32(const void* p) {
    uint32_t a;
    asm("{ .reg .u64 t; cvta.to.shared.u64 t, %1; cvt.u32.u64 %0, t; }" : "=r"(a) : "l"(p));
    return a;
}
#define MBAR_INIT(a, c) asm volatile("mbarrier.init.shared.b64 [%0], %1;" :: "r"(a), "r"(c) : "memory")
#define MBAR_EXPECT_TX(a, b) asm volatile("mbarrier.arrive.expect_tx.shared.b64 _, [%0], %1;" :: "r"(a), "r"(b) : "memory")
#define MBAR_WAIT(a, p) do { \
    asm volatile("{\n\t.reg .pred P1;\n\tWL_%=:\n\t" \
        "mbarrier.try_wait.parity.acquire.cta.shared::cta.b64 P1, [%0], %1, 0x989680;\n\t" \
        "@P1 bra.uni WD_%=;\n\tbra.uni WL_%=;\n\tWD_%=:\n\t}" :: "r"(a), "r"(p) : "memory"); \
} while (0)
#define TMA_LOAD_2D(dst, tm, cx, cy, mb) \
    asm volatile("cp.async.bulk.tensor.2d.shared::cta.global.tile.mbarrier::complete_tx::bytes " \
        "[%0], [%1, {%2, %3}], [%4];" :: "r"(dst), "l"(tm), "r"(cx), "r"(cy), "r"(mb) : "memory")

#ifdef HAS_TC
#define TC_ALLOC(s, n) asm volatile("tcgen05.alloc.cta_group::1.sync.aligned.shared::cta.b32 [%0], %1;" :: "r"(s), "r"(n) : "memory")
#define TC_RELINQ()    asm volatile("tcgen05.relinquish_alloc_permit.cta_group::1.sync.aligned;")
#define TC_DEALLOC(t, n) asm volatile("tcgen05.dealloc.cta_group::1.sync.aligned.b32 %0, %1;" :: "r"(t), "r"(n))
#define TC_COMMIT(mb)  asm volatile("tcgen05.commit.cta_group::1.mbarrier::arrive::one.shared::cluster.b64 [%0];" :: "r"(mb) : "memory")
#define TC_FENCE_AFTER() asm volatile("tcgen05.fence::after_thread_sync;" ::: "memory")
#define TC_WAIT_LD()   asm volatile("tcgen05.wait::ld.sync.aligned;" ::: "memory")

__device__ __forceinline__ void mma_f16_ss(uint32_t d, uint64_t ad, uint64_t bd,
                                           uint32_t idesc, uint32_t accf) {
    asm volatile("{\n\t.reg .pred p;\n\tsetp.ne.u32 p, %4, 0;\n\t"
        "tcgen05.mma.cta_group::1.kind::f16 [%0], %1, %2, %3, {%5,%5,%5,%5}, p;\n\t}"
        :: "r"(d), "l"(ad), "l"(bd), "r"(idesc), "r"(accf), "r"(0u) : "memory");
}
#define TC_LD_X32(r, t) \
    asm volatile("tcgen05.ld.sync.aligned.32x32b.x32.b32 " \
        "{%0,%1,%2,%3,%4,%5,%6,%7,%8,%9,%10,%11,%12,%13,%14,%15," \
        "%16,%17,%18,%19,%20,%21,%22,%23,%24,%25,%26,%27,%28,%29,%30,%31}, [%32];" \
        : "=r"((r)[0]),"=r"((r)[1]),"=r"((r)[2]),"=r"((r)[3]),"=r"((r)[4]),"=r"((r)[5]),"=r"((r)[6]),"=r"((r)[7]), \
          "=r"((r)[8]),"=r"((r)[9]),"=r"((r)[10]),"=r"((r)[11]),"=r"((r)[12]),"=r"((r)[13]),"=r"((r)[14]),"=r"((r)[15]), \
          "=r"((r)[16]),"=r"((r)[17]),"=r"((r)[18]),"=r"((r)[19]),"=r"((r)[20]),"=r"((r)[21]),"=r"((r)[22]),"=r"((r)[23]), \
          "=r"((r)[24]),"=r"((r)[25]),"=r"((r)[26]),"=r"((r)[27]),"=r"((r)[28]),"=r"((r)[29]),"=r"((r)[30]),"=r"((r)[31]) \
        : "r"(t))
#endif

#define DESC_BASE ((2ull << 61) | (1ull << 46) | (64ull << 32) | (1ull << 16))
#define MAKE_DESC(a) (DESC_BASE | ((uint64_t)((a) >> 4) & 0x3FFF))
#define IDESC_BIG 0x8400010u    /* cg1: F32 acc, f16, M=128, N=256 */
#define IDESC_RP  0x8180010u    /* cg1: F32 acc, f16, M=128, N=96  */

// ---------------- k_prep: fused conv + weight builds ----------------
#define CONV_BLKS 32768
#define WB_BLKS   (CDIM * KPAD / 256)
#define WC_BLKS   (NRP * CDIM / 256)
#define BBE_BLKS  4
#define PREP_BLKS (CONV_BLKS + WB_BLKS + WC_BLKS + BBE_BLKS)

__global__ __launch_bounds__(256) void k_prep(const float* __restrict__ x,
                                              const float* __restrict__ Wb,
                                              const float* __restrict__ Wup,
                                              const float* __restrict__ Wout,
                                              const float* __restrict__ Wdown,
                                              const float* __restrict__ Wxp,
                                              const float* __restrict__ bb,
                                              const float* __restrict__ bout) {
    const int bid = blockIdx.x, tid = threadIdx.x;
    if (bid < CONV_BLKS) {
        size_t base = ((size_t)bid * 256 + tid) * 8;
        size_t row = base >> 10, col = base & 1023;
        float4 v0 = *(const float4*)(x + base);
        float4 v1 = *(const float4*)(x + base + 4);
        __half2 h0 = __floats2half2_rn(v0.x, v0.y);
        __half2 h1 = __floats2half2_rn(v0.z, v0.w);
        __half2 h2 = __floats2half2_rn(v1.x, v1.y);
        __half2 h3 = __floats2half2_rn(v1.z, v1.w);
        uint4 u;
        u.x = *(uint32_t*)&h0; u.y = *(uint32_t*)&h1;
        u.z = *(uint32_t*)&h2; u.w = *(uint32_t*)&h3;
        *(uint4*)(g_xh + row * KPAD + col) = u;
    } else if (bid < CONV_BLKS + WB_BLKS) {
        int idx = (bid - CONV_BLKS) * 256 + tid;
        int n = idx / KPAD, c = idx % KPAD;
        float v;
        if (c < 1024) {
            v = Wb[(size_t)n * 1024 + c];
        } else if (c < 1056) {
            int q = c - 1024;
            float s = 0.f;
#pragma unroll
            for (int r = 0; r < RANK; r++)
                s = fmaf(Wup[(size_t)n * RANK + r], Wout[r * RANK + q], s);
            v = SCALING * s;
        } else v = 0.f;
        g_wh[idx] = __float2half_rn(v);
    } else if (bid < CONV_BLKS + WB_BLKS + WC_BLKS) {
        int idx = (bid - CONV_BLKS - WB_BLKS) * 256 + tid;
        int row = idx >> 10, c = idx & 1023;
        float v;
        if (row < RANK) {
            v = Wdown[(size_t)row * CDIM + c];
        } else {
            int i = row - RANK;
            float s = 0.f;
#pragma unroll
            for (int r = 0; r < RANK; r++)
                s = fmaf(Wxp[i * RANK + r], Wdown[(size_t)r * CDIM + c], s);
            v = s;
        }
        g_wch[idx] = __float2half_rn(v);
    } else {
        int n = (bid - CONV_BLKS - WB_BLKS - WC_BLKS) * 256 + tid;
        if (n < CDIM) {
            float s = 0.f;
#pragma unroll
            for (int r = 0; r < RANK; r++)
                s = fmaf(Wup[(size_t)n * RANK + r], bout[r], s);
            g_bbe[n] = bb[n] + SCALING * s;
        }
    }
}

// ---------------- k_red: rp = xh @ Wcomb.T  (M=65536, N=96, K=1024) ----------------
#define R_KCH    64
#define R_NCH    16
#define R_ABYTES (128 * 128)
#define R_BBYTES (NRP * 128)
#define R_STG    (R_ABYTES + R_BBYTES)
#define R_SMEM   (1024 + 3 * R_STG)

__global__ __launch_bounds__(128) void k_red(const __grid_constant__ CUtensorMap tmA,
                                             const __grid_constant__ CUtensorMap tmWc) {
#ifdef HAS_TC
    extern __shared__ __align__(1024) char smem[];
    const uint32_t sbase = smem_u32(smem);
    const uint32_t tslot = sbase;
    const uint32_t fullb = sbase + 16;
    const uint32_t emptb = sbase + 48;
    const uint32_t doneb = sbase + 80;
    const int tid = threadIdx.x, wid = tid >> 5, lane = tid & 31;
    const int m0 = blockIdx.x * 128;

    if (tid == 0) {
        MBAR_INIT(fullb, 1); MBAR_INIT(fullb + 8, 1); MBAR_INIT(fullb + 16, 1);
        MBAR_INIT(emptb, 1); MBAR_INIT(emptb + 8, 1); MBAR_INIT(emptb + 16, 1);
        MBAR_INIT(doneb, 1);
    }
    if (wid == 0) { TC_ALLOC(tslot, 128); TC_RELINQ(); }
    __syncthreads();
    uint32_t tmem;
    asm volatile("ld.shared.b32 %0, [%1];" : "=r"(tmem) : "r"(tslot));

    if (tid == 0) {
        int eph[3] = {1, 1, 1};
        for (int c = 0; c < R_NCH; c++) {
            int s = c % 3;
            MBAR_WAIT(emptb + s * 8, eph[s]); eph[s] ^= 1;
            uint32_t aA = sbase + 1024 + s * R_STG;
            MBAR_EXPECT_TX(fullb + s * 8, R_STG);
            TMA_LOAD_2D(aA, &tmA, c * R_KCH, m0, fullb + s * 8);
            TMA_LOAD_2D(aA + R_ABYTES, &tmWc, c * R_KCH, 0, fullb + s * 8);
        }
    } else if (tid == 33) {
        int fph[3] = {0, 0, 0};
        for (int c = 0; c < R_NCH; c++) {
            int s = c % 3;
            MBAR_WAIT(fullb + s * 8, fph[s]); fph[s] ^= 1;
            uint32_t aA = sbase + 1024 + s * R_STG;
            uint64_t ad = MAKE_DESC(aA), bd = MAKE_DESC(aA + R_ABYTES);
#pragma unroll
            for (int k = 0; k < 4; k++)
                mma_f16_ss(tmem, ad + 2 * k, bd + 2 * k, IDESC_RP, (c | k) != 0);
            TC_COMMIT(emptb + s * 8);
        }
        TC_COMMIT(doneb);
    }

    MBAR_WAIT(doneb, 0);
    TC_FENCE_AFTER();

    float* gr = g_rp + (size_t)(m0 + wid * 32 + lane) * NRP;
#pragma unroll
    for (int cb = 0; cb < 3; cb++) {
        uint32_t r[32];
        TC_LD_X32(r, tmem + cb * 32);
        TC_WAIT_LD();
#pragma unroll
        for (int j = 0; j < 32; j += 4) {
            float4 v;
            v.x = __uint_as_float(r[j]);     v.y = __uint_as_float(r[j + 1]);
            v.z = __uint_as_float(r[j + 2]); v.w = __uint_as_float(r[j + 3]);
            *(float4*)(gr + cb * 32 + j) = v;
        }
    }
    __syncthreads();
    if (wid == 0) TC_DEALLOC(tmem, 128);
#else
    const int tid = threadIdx.x;
    const int m0 = blockIdx.x * 128;
    for (int e = tid; e < 128 * NRP; e += 128) {
        int r = e / NRP, n = e % NRP;
        float acc = 0.f;
        for (int k = 0; k < CDIM; k++)
            acc = fmaf(__half2float(g_xh[(size_t)(m0 + r) * KPAD + k]),
                       __half2float(g_wch[(size_t)n * CDIM + k]), acc);
        g_rp[(size_t)(m0 + r) * NRP + n] = acc;
    }
#endif
}

// ---------------- k_ssm: pure recurrence ----------------
__device__ __forceinline__ float softplusf(float v) {
    return (v > 15.0f) ? v : log1pf(__expf(v));
}

__global__ __launch_bounds__(256) void k_ssm(const float* __restrict__ A_log,
                                             const float* __restrict__ Dp,
                                             const float* __restrict__ bxp) {
    const int tid  = threadIdx.x;
    const int lane = tid & 31;
    const int seq  = (blockIdx.x * blockDim.x + tid) >> 5;
    const int b = seq >> 10, p = seq & 1023;

    float An[DST];
#pragma unroll
    for (int s = 0; s < DST; s++) An[s] = -__expf(__ldg(A_log + lane * 16 + s));
    const float Dpr  = __ldg(Dp + lane);
    const float bx0  = __ldg(bxp + lane);
    const float bx1  = __ldg(bxp + 32 + lane);
    float h[DST];
#pragma unroll
    for (int s = 0; s < DST; s++) h[s] = 0.f;

    for (int t = 0; t < TT; t++) {
        size_t m = (size_t)(b * TT + t) * PDIM + p;
        const float* rp = g_rp + m * NRP;
        float xv = rp[lane];
        float p0 = rp[32 + lane] + bx0;
        float p1 = rp[64 + lane] + bx1;
        float dlt = softplusf(p0);
        float y = Dpr * xv;
#pragma unroll
        for (int s = 0; s < DST; s++) {
            float Bs_ = __shfl_sync(FULLMASK, p1, s);
            float Cs_ = __shfl_sync(FULLMASK, p1, 16 + s);
            float Ab  = __expf(dlt * An[s]);
            h[s] = fmaf(Ab, h[s], dlt * Bs_ * xv);
            y    = fmaf(h[s], Cs_, y);
        }
        g_xh[m * KPAD + 1024 + lane] = __float2half_rn(y);
        g_xh[m * KPAD + 1056 + lane] = __float2half_rn(0.f);
    }
}

// ---------------- k_big: cg1, 256x256 tile per CTA (2 MMAs, 512 TMEM cols) ----------
#define KCH       64
#define NCHUNK    17
#define A_BYTES   (256 * 128)              // 32768
#define B_BYTES   (256 * 128)              // 32768
#define STG_BYTES (A_BYTES + B_BYTES)      // 65536
#define NSTG      3
#define SMEM_DYN  (1024 + NSTG * STG_BYTES)  // 197632

__global__ __launch_bounds__(256, 1) void k_big(const __grid_constant__ CUtensorMap tmA,
                                                const __grid_constant__ CUtensorMap tmB,
                                                float* __restrict__ out) {
#ifdef HAS_TC
    extern __shared__ __align__(1024) char smem[];
    const uint32_t sbase = smem_u32(smem);
    const uint32_t tslot = sbase;
    const uint32_t fullb = sbase + 16;
    const uint32_t emptb = sbase + 48;
    const uint32_t doneb = sbase + 80;

    const int tid = threadIdx.x;
    const int wid = tid >> 5, lane = tid & 31;
    const int m0 = blockIdx.y * 256;
    const int n0 = blockIdx.x * 256;

    if (tid == 0) {
        MBAR_INIT(fullb, 1); MBAR_INIT(fullb + 8, 1); MBAR_INIT(fullb + 16, 1);
        MBAR_INIT(emptb, 1); MBAR_INIT(emptb + 8, 1); MBAR_INIT(emptb + 16, 1);
        MBAR_INIT(doneb, 1);
    }
    if (wid == 0) { TC_ALLOC(tslot, 512); TC_RELINQ(); }
    __syncthreads();
    uint32_t tmem;
    asm volatile("ld.shared.b32 %0, [%1];" : "=r"(tmem) : "r"(tslot));

    if (tid == 0) {                 // producer
        int eph[3] = {1, 1, 1};
        for (int c = 0; c < NCHUNK; c++) {
            int s = c % 3;
            MBAR_WAIT(emptb + s * 8, eph[s]); eph[s] ^= 1;
            uint32_t aA = sbase + 1024 + s * STG_BYTES;
            MBAR_EXPECT_TX(fullb + s * 8, STG_BYTES);
            TMA_LOAD_2D(aA, &tmA, c * KCH, m0, fullb + s * 8);            // 256 A rows
            TMA_LOAD_2D(aA + A_BYTES, &tmB, c * KCH, n0, fullb + s * 8);  // 256 B rows
        }
    } else if (tid == 32) {         // MMA issuer: 2 accumulators share B
        int fph[3] = {0, 0, 0};
        for (int c = 0; c < NCHUNK; c++) {
            int s = c % 3;
            MBAR_WAIT(fullb + s * 8, fph[s]); fph[s] ^= 1;
            uint32_t aA = sbase + 1024 + s * STG_BYTES;
            uint64_t ad0 = MAKE_DESC(aA);
            uint64_t ad1 = MAKE_DESC(aA + 128 * 128);
            uint64_t bd  = MAKE_DESC(aA + A_BYTES);
            uint32_t acf = (c != 0);
#pragma unroll
            for (int k = 0; k < 4; k++) {
                uint32_t f = acf | (k != 0);
                mma_f16_ss(tmem,       ad0 + 2 * k, bd + 2 * k, IDESC_BIG, f);
                mma_f16_ss(tmem + 256, ad1 + 2 * k, bd + 2 * k, IDESC_BIG, f);
            }
            TC_COMMIT(emptb + s * 8);
        }
        TC_COMMIT(doneb);
    }

    MBAR_WAIT(doneb, 0);
    TC_FENCE_AFTER();

    const int half = wid >> 2;
    const int row  = m0 + half * 128 + (wid & 3) * 32 + lane;
    const uint32_t sacc = tmem + half * 256;
#pragma unroll
    for (int cb = 0; cb < 8; cb++) {
        uint32_t r[32];
        TC_LD_X32(r, sacc + cb * 32);
        TC_WAIT_LD();
        const int col = n0 + cb * 32;
        float* orow = out + (size_t)row * CDIM + col;
#pragma unroll
        for (int j = 0; j < 32; j += 4) {
            float4 v;
            v.x = __uint_as_float(r[j])     + g_bbe[col + j];
            v.y = __uint_as_float(r[j + 1]) + g_bbe[col + j + 1];
            v.z = __uint_as_float(r[j + 2]) + g_bbe[col + j + 2];
            v.w = __uint_as_float(r[j + 3]) + g_bbe[col + j + 3];
            *(float4*)(orow + j) = v;
        }
    }

    __syncthreads();
    if (wid == 0) TC_DEALLOC(tmem, 512);
#else
    const int tid = threadIdx.x;
    const int m0 = blockIdx.y * 256;
    const int n0 = blockIdx.x * 256;
    for (int e = tid; e < 256 * 256; e += 256) {
        int r = e >> 8, c = e & 255;
        const __half2* a = (const __half2*)(g_xh + (size_t)(m0 + r) * KPAD);
        const __half2* w = (const __half2*)(g_wh + (size_t)(n0 + c) * KPAD);
        float acc = 0.f;
        for (int k = 0; k < KPAD / 2; k++) {
            float2 av = __half22float2(a[k]);
            float2 wv = __half22float2(w[k]);
            acc = fmaf(av.x, wv.x, acc);
            acc = fmaf(av.y, wv.y, acc);
        }
        out[(size_t)(m0 + r) * CDIM + n0 + c] = acc + g_bbe[n0 + c];
    }
#endif
}

// ---------------- Host ----------------
typedef CUresult (*EncodeFn)(CUtensorMap*, CUtensorMapDataType, cuuint32_t, void*,
                             const cuuint64_t*, const cuuint64_t*, const cuuint32_t*,
                             const cuuint32_t*, CUtensorMapInterleave, CUtensorMapSwizzle,
                             CUtensorMapL2promotion, CUtensorMapFloatOOBfill);

static void make_map(EncodeFn enc, CUtensorMap* tm, void* ptr, uint64_t d0, uint64_t d1,
                     uint32_t b0, uint32_t b1) {
    cuuint64_t dims[2]    = {d0, d1};
    cuuint64_t strides[1] = {d0 * 2};
    cuuint32_t box[2]     = {b0, b1};
    cuuint32_t es[2]      = {1, 1};
    enc(tm, CU_TENSOR_MAP_DATA_TYPE_FLOAT16, 2, ptr, dims, strides, box, es,
        CU_TENSOR_MAP_INTERLEAVE_NONE, CU_TENSOR_MAP_SWIZZLE_128B,
        CU_TENSOR_MAP_L2_PROMOTION_L2_128B, CU_TENSOR_MAP_FLOAT_OOB_FILL_NONE);
}

extern "C" void kernel_launch(void* const* d_in, const int* in_sizes, int n_in,
                              void* d_out, int out_size) {
    const float* x     = (const float*)d_in[0];
    const float* Wb    = (const float*)d_in[1];
    const float* bb    = (const float*)d_in[2];
    const float* Wdown = (const float*)d_in[3];
    const float* Wup   = (const float*)d_in[4];
    const float* A_log = (const float*)d_in[5];
    const float* Dp    = (const float*)d_in[6];
    const float* Wxp   = (const float*)d_in[7];
    const float* bxp   = (const float*)d_in[8];
    const float* Wout  = (const float*)d_in[9];
    const float* bout  = (const float*)d_in[10];
    float* out = (float*)d_out;

    void* fn = nullptr;
    cudaDriverEntryPointQueryResult qr;
    cudaGetDriverEntryPointByVersion("cuTensorMapEncodeTiled", &fn, CUDART_VERSION,
                                     cudaEnableDefault, &qr);
    EncodeFn enc = (EncodeFn)fn;

    void *xh_ptr, *wh_ptr, *wch_ptr;
    cudaGetSymbolAddress(&xh_ptr,  g_xh);
    cudaGetSymbolAddress(&wh_ptr,  g_wh);
    cudaGetSymbolAddress(&wch_ptr, g_wch);

    // SEPARATE maps: k_big uses 256-row boxes, k_red uses 128-row A box (R16 bug fix)
    CUtensorMap tmA256, tmB256, tmA128, tmWc;
    make_map(enc, &tmA256, xh_ptr,  KPAD, MROWS, KCH,   256);
    make_map(enc, &tmB256, wh_ptr,  KPAD, CDIM,  KCH,   256);
    make_map(enc, &tmA128, xh_ptr,  KPAD, MROWS, R_KCH, 128);
    make_map(enc, &tmWc,   wch_ptr, CDIM, NRP,   R_KCH, NRP);

    cudaFuncSetAttribute(k_big, cudaFuncAttributeMaxDynamicSharedMemorySize, SMEM_DYN);
    cudaFuncSetAttribute(k_red, cudaFuncAttributeMaxDynamicSharedMemorySize, R_SMEM);

    k_prep<<<PREP_BLKS, 256>>>(x, Wb, Wup, Wout, Wdown, Wxp, bb, bout);
    k_red<<<MROWS / 128, 128, R_SMEM>>>(tmA128, tmWc);
    k_ssm<<<(MROWS / TT) * 32 / 256, 256>>>(A_log, Dp, bxp);

    dim3 grid(CDIM / 256, MROWS / 256);
    k_big<<<grid, 256, SMEM_DYN>>>(tmA256, tmB256, out);
}